// round 2
// baseline (speedup 1.0000x reference)
#include <cuda_runtime.h>
#include <math.h>

#define B_   16
#define C_   256
#define H_   64
#define HW_  4096
#define L_   40
#define TD_  768
#define EMB_ 392
#define NC_  8

// ---- scratch (no cudaMalloc allowed) ----
__device__ float g_bufA[B_*C_*HW_];   // 67 MB
__device__ float g_bufB[B_*C_*HW_];   // 67 MB
__device__ float g_g[B_*HW_];
__device__ float g_bmax[B_*HW_];
__device__ float g_S[B_*C_*9];
__device__ float g_yc[B_*NC_];
__device__ float g_xc[B_*NC_];
__device__ float g_sy[B_*NC_];

__device__ __forceinline__ float sigmf(float x){ return 1.f/(1.f+expf(-x)); }

// ---------------- K1: language path -> yc/xc ----------------
__global__ void k_lang(const float* __restrict__ flang, const int* __restrict__ wmask,
                       const float* __restrict__ W1, const float* __restrict__ b1,
                       const float* __restrict__ W2, const float* __restrict__ b2)
{
    __shared__ float incs[L_];
    __shared__ float favg[TD_];
    __shared__ float e1s[EMB_];
    __shared__ float mapv[16];
    __shared__ float sinv;
    int b = blockIdx.x, tid = threadIdx.x;
    if (tid == 0){
        float cs[L_]; float c = 0.f;
        for (int l = 0; l < L_; l++){ c += (float)wmask[b*L_+l]; cs[l] = c; }
        float tot = c, s = 0.f;
        for (int l = 0; l < L_; l++){
            float m = (float)wmask[b*L_+l];
            float v = (cs[l] > 1.f && cs[l] < tot) ? m : 0.f;
            incs[l] = v; s += v;
        }
        sinv = 1.f/s;
    }
    __syncthreads();
    for (int d = tid; d < TD_; d += 256){
        float a = 0.f;
        for (int l = 0; l < L_; l++) a += flang[((size_t)b*L_+l)*TD_+d]*incs[l];
        favg[d] = a*sinv;
    }
    __syncthreads();
    for (int j = tid; j < EMB_; j += 256){
        float a = b1[j];
        const float* w = W1 + (size_t)j*TD_;
        for (int d = 0; d < TD_; d++) a = fmaf(favg[d], w[d], a);
        e1s[j] = a;
    }
    __syncthreads();
    if (tid < 16){
        float a = b2[tid];
        const float* w = W2 + (size_t)tid*EMB_;
        for (int j = 0; j < EMB_; j++) a = fmaf(e1s[j], w[j], a);
        mapv[tid] = sigmf(a);
    }
    __syncthreads();
    if (tid < NC_){
        float y = mapv[2*tid]   * (float)H_;
        float x = mapv[2*tid+1] * (float)H_;
        g_yc[b*NC_+tid] = (float)(int)y;   // trunc like astype(int32)
        g_xc[b*NC_+tid] = (float)(int)x;
    }
}

// ---------------- K2: 9 shifted window sums S[b,c,dy,dx] ----------------
__global__ void k_ssum(const float* __restrict__ img)
{
    int bc = blockIdx.x;            // b*C + c
    int tid = threadIdx.x;
    const float* p = img + (size_t)bc*HW_;
    float acc[9];
    #pragma unroll
    for (int j = 0; j < 9; j++) acc[j] = 0.f;
    for (int i = tid; i < HW_; i += 128){
        int h = i >> 6, w = i & 63;
        float v = p[i];
        #pragma unroll
        for (int dy = 0; dy < 3; dy++){
            bool oy = (h - dy) >= 0 && (h - dy) <= 61;
            #pragma unroll
            for (int dx = 0; dx < 3; dx++){
                bool ox = (w - dx) >= 0 && (w - dx) <= 61;
                if (oy && ox) acc[dy*3+dx] += v;
            }
        }
    }
    __shared__ float red[9][128];
    #pragma unroll
    for (int j = 0; j < 9; j++) red[j][tid] = acc[j];
    __syncthreads();
    for (int off = 64; off > 0; off >>= 1){
        if (tid < off){
            #pragma unroll
            for (int j = 0; j < 9; j++) red[j][tid] += red[j][tid+off];
        }
        __syncthreads();
    }
    if (tid < 9) g_S[(size_t)bc*9 + tid] = red[tid][0];
}

// ---------------- K3: sigma_y[b,nc] ----------------
__global__ void k_sigma(const float* __restrict__ Ws, const float* __restrict__ bs,
                        const float* __restrict__ sigma_w)
{
    int bn = blockIdx.x; int b = bn >> 3; int nc = bn & 7;
    int tid = threadIdx.x;
    const float* w = Ws  + (size_t)nc*C_*9;
    const float* s = g_S + (size_t)b*C_*9;
    float a = 0.f;
    for (int i = tid; i < C_*9; i += 128) a = fmaf(w[i], s[i], a);
    __shared__ float red[128];
    red[tid] = a; __syncthreads();
    for (int off = 64; off > 0; off >>= 1){
        if (tid < off) red[tid] += red[tid+off];
        __syncthreads();
    }
    if (tid == 0){
        float mean = red[0]*(1.f/3844.f) + bs[nc];
        g_sy[bn] = sigma_w[0]*(float)H_*sigmf(mean);
    }
}

// ---------------- K4: gaussian weights -> gamma/beta -> g, bmax ----------------
__global__ void k_gbmax(const float* __restrict__ Wg, const float* __restrict__ sg, const float* __restrict__ bg,
                        const float* __restrict__ Wb, const float* __restrict__ sb, const float* __restrict__ bb,
                        const float* __restrict__ sigma_w)
{
    int blk = blockIdx.x; int b = blk >> 4; int chunk = blk & 15;
    int tid = threadIdx.x;
    __shared__ float syc[8], sxc[8], ssy[8], swg[64], swb[64], ssg[8], sbgs[8], ssb[8], sbbs[8];
    if (tid < 8){
        syc[tid] = g_yc[b*8+tid]; sxc[tid] = g_xc[b*8+tid]; ssy[tid] = g_sy[b*8+tid];
        ssg[tid] = sg[tid]; sbgs[tid] = bg[tid]; ssb[tid] = sb[tid]; sbbs[tid] = bb[tid];
    }
    if (tid < 64){ swg[tid] = Wg[tid]; swb[tid] = Wb[tid]; }
    __syncthreads();
    float sx = sigma_w[0]*(float)H_;
    float inv2sx2 = 1.f/(2.f*sx*sx);
    int p = chunk*256 + tid;
    float fh = (float)(p >> 6), fw = (float)(p & 63);
    float wv[8];
    #pragma unroll
    for (int i = 0; i < 8; i++){
        float dy = fh - syc[i], dx = fw - sxc[i];
        float sy = ssy[i];
        wv[i] = expf(-(dy*dy/(2.f*sy*sy) + dx*dx*inv2sx2));
    }
    float gsum = 0.f, bmx = -1e30f;
    #pragma unroll
    for (int j = 0; j < 8; j++){
        float ag = 0.f, ab = 0.f;
        #pragma unroll
        for (int i = 0; i < 8; i++){
            ag = fmaf(swg[j*8+i], wv[i], ag);
            ab = fmaf(swb[j*8+i], wv[i], ab);
        }
        float yg = fmaf(ag, ssg[j], sbgs[j]);
        gsum += tanhf(yg*sigmf(yg));
        float yb = fmaf(ab, ssb[j], sbbs[j]);
        bmx = fmaxf(bmx, tanhf(yb*sigmf(yb)));
    }
    g_g[(size_t)b*HW_+p]    = gsum*0.125f;
    g_bmax[(size_t)b*HW_+p] = bmx;
}

// ---------------- 128x128x8 SGEMM with fused epilogues ----------------
// EPI 0: map_visu path: y=acc*s+b; silu; tanh; out = g*t + bmax
// EPI 1: cbs: y=acc*s+b; out = silu(y)
// EPI 2: final: y=acc+b; out = (1+aw)*img + (1-aw)*y
template<int EPI>
__global__ __launch_bounds__(256) void k_gemm(
    const float* __restrict__ A, const float* __restrict__ X, float* __restrict__ Y,
    const float* __restrict__ scale, const float* __restrict__ bias,
    const float* __restrict__ img, const float* __restrict__ awp)
{
    __shared__ float As[8][128];
    __shared__ float Bs[8][128];
    int b  = blockIdx.z;
    int m0 = blockIdx.y*128, n0 = blockIdx.x*128;
    const float* Xb = X + (size_t)b*C_*HW_;
    float* Yb = Y + (size_t)b*C_*HW_;
    int tid = threadIdx.x;
    int tx = tid & 15, ty = tid >> 4;
    int arow = tid >> 1, acol = (tid & 1)*4;
    int brow = tid >> 5, bcol = (tid & 31)*4;

    float acc[8][8];
    #pragma unroll
    for (int i = 0; i < 8; i++)
        #pragma unroll
        for (int j = 0; j < 8; j++) acc[i][j] = 0.f;

    for (int k0 = 0; k0 < C_; k0 += 8){
        float4 av = *(const float4*)(A  + (size_t)(m0+arow)*C_  + k0 + acol);
        float4 bv = *(const float4*)(Xb + (size_t)(k0+brow)*HW_ + n0 + bcol);
        __syncthreads();
        As[acol+0][arow] = av.x; As[acol+1][arow] = av.y;
        As[acol+2][arow] = av.z; As[acol+3][arow] = av.w;
        *(float4*)(&Bs[brow][bcol]) = bv;
        __syncthreads();
        #pragma unroll
        for (int kk = 0; kk < 8; kk++){
            float a[8], bq[8];
            *(float4*)(a)    = *(const float4*)(&As[kk][ty*8]);
            *(float4*)(a+4)  = *(const float4*)(&As[kk][ty*8+4]);
            *(float4*)(bq)   = *(const float4*)(&Bs[kk][tx*8]);
            *(float4*)(bq+4) = *(const float4*)(&Bs[kk][tx*8+4]);
            #pragma unroll
            for (int i = 0; i < 8; i++)
                #pragma unroll
                for (int j = 0; j < 8; j++) acc[i][j] = fmaf(a[i], bq[j], acc[i][j]);
        }
    }

    float aw = 0.f;
    if (EPI == 2) aw = tanhf(awp[0]);
    float gn[8], bn[8];
    if (EPI == 0){
        #pragma unroll
        for (int j = 0; j < 8; j++){
            int n = n0 + tx*8 + j;
            gn[j] = g_g[(size_t)b*HW_+n];
            bn[j] = g_bmax[(size_t)b*HW_+n];
        }
    }
    #pragma unroll
    for (int i = 0; i < 8; i++){
        int m = m0 + ty*8 + i;
        float sm = (EPI == 2) ? 1.f : scale[m];
        float bm = bias[m];
        float o[8];
        #pragma unroll
        for (int j = 0; j < 8; j++){
            float y = fmaf(acc[i][j], sm, bm);
            if (EPI == 0){
                float s = y*sigmf(y);
                float t = tanhf(s);
                o[j] = fmaf(gn[j], t, bn[j]);
            } else if (EPI == 1){
                o[j] = y*sigmf(y);
            } else {
                int n = n0 + tx*8 + j;
                float iv = img[((size_t)b*C_ + m)*HW_ + n];
                o[j] = (1.f+aw)*iv + (1.f-aw)*y;
            }
        }
        float* dst = Yb + (size_t)m*HW_ + n0 + tx*8;
        *(float4*)dst     = make_float4(o[0], o[1], o[2], o[3]);
        *(float4*)(dst+4) = make_float4(o[4], o[5], o[6], o[7]);
    }
}

// ---------------- implicit-GEMM 3x3 conv (pad=1), K=2304, cbs epilogue ----------------
__global__ __launch_bounds__(256) void k_conv3(
    const float* __restrict__ A,   // [256][2304] = Wf2
    const float* __restrict__ X, float* __restrict__ Y,
    const float* __restrict__ scale, const float* __restrict__ bias)
{
    __shared__ float As[8][128];
    __shared__ float Bs[8][128];
    int b  = blockIdx.z;
    int m0 = blockIdx.y*128, n0 = blockIdx.x*128;
    const float* Xb = X + (size_t)b*C_*HW_;
    float* Yb = Y + (size_t)b*C_*HW_;
    int tid = threadIdx.x;
    int tx = tid & 15, ty = tid >> 4;
    int arow = tid >> 1, acol = (tid & 1)*4;
    int brow = tid >> 5, bcol = (tid & 31)*4;

    float acc[8][8];
    #pragma unroll
    for (int i = 0; i < 8; i++)
        #pragma unroll
        for (int j = 0; j < 8; j++) acc[i][j] = 0.f;

    for (int k0 = 0; k0 < 2304; k0 += 8){
        float4 av = *(const float4*)(A + (size_t)(m0+arow)*2304 + k0 + acol);
        int kk = k0 + brow;
        int c  = kk/9; int r = kk - c*9;
        int ry = r/3 - 1;
        int rx = (r - (r/3)*3) - 1;
        float bvv[4];
        #pragma unroll
        for (int j = 0; j < 4; j++){
            int n = n0 + bcol + j;
            int h = (n >> 6) + ry, w = (n & 63) + rx;
            bool ok = (unsigned)h < 64u && (unsigned)w < 64u;
            bvv[j] = ok ? Xb[(size_t)c*HW_ + (h << 6) + w] : 0.f;
        }
        __syncthreads();
        As[acol+0][arow] = av.x; As[acol+1][arow] = av.y;
        As[acol+2][arow] = av.z; As[acol+3][arow] = av.w;
        Bs[brow][bcol+0] = bvv[0]; Bs[brow][bcol+1] = bvv[1];
        Bs[brow][bcol+2] = bvv[2]; Bs[brow][bcol+3] = bvv[3];
        __syncthreads();
        #pragma unroll
        for (int kk2 = 0; kk2 < 8; kk2++){
            float a[8], bq[8];
            *(float4*)(a)    = *(const float4*)(&As[kk2][ty*8]);
            *(float4*)(a+4)  = *(const float4*)(&As[kk2][ty*8+4]);
            *(float4*)(bq)   = *(const float4*)(&Bs[kk2][tx*8]);
            *(float4*)(bq+4) = *(const float4*)(&Bs[kk2][tx*8+4]);
            #pragma unroll
            for (int i = 0; i < 8; i++)
                #pragma unroll
                for (int j = 0; j < 8; j++) acc[i][j] = fmaf(a[i], bq[j], acc[i][j]);
        }
    }

    #pragma unroll
    for (int i = 0; i < 8; i++){
        int m = m0 + ty*8 + i;
        float sm = scale[m], bm = bias[m];
        float o[8];
        #pragma unroll
        for (int j = 0; j < 8; j++){
            float y = fmaf(acc[i][j], sm, bm);
            o[j] = y*sigmf(y);
        }
        float* dst = Yb + (size_t)m*HW_ + n0 + tx*8;
        *(float4*)dst     = make_float4(o[0], o[1], o[2], o[3]);
        *(float4*)(dst+4) = make_float4(o[4], o[5], o[6], o[7]);
    }
}

// ---------------- channelwise L2 norm ----------------
__global__ void k_l2norm(const float* __restrict__ X, float* __restrict__ Y)
{
    int q = blockIdx.x*128 + threadIdx.x;   // < B*HW
    int b = q >> 12, p = q & 4095;
    const float* xp = X + (size_t)b*C_*HW_ + p;
    float a0 = 0.f, a1 = 0.f, a2 = 0.f, a3 = 0.f;
    #pragma unroll 8
    for (int c = 0; c < C_; c += 4){
        float v0 = xp[(size_t)c*HW_];
        float v1 = xp[(size_t)(c+1)*HW_];
        float v2 = xp[(size_t)(c+2)*HW_];
        float v3 = xp[(size_t)(c+3)*HW_];
        a0 = fmaf(v0, v0, a0); a1 = fmaf(v1, v1, a1);
        a2 = fmaf(v2, v2, a2); a3 = fmaf(v3, v3, a3);
    }
    float n = sqrtf((a0+a1)+(a2+a3));
    float inv = 1.f/fmaxf(n, 1e-12f);
    float* yp = Y + (size_t)b*C_*HW_ + p;
    #pragma unroll 8
    for (int c = 0; c < C_; c++) yp[(size_t)c*HW_] = xp[(size_t)c*HW_]*inv;
}

extern "C" void kernel_launch(void* const* d_in, const int* in_sizes, int n_in,
                              void* d_out, int out_size)
{
    const float* img    = (const float*)d_in[0];
    const float* flang  = (const float*)d_in[1];
    const int*   wmask  = (const int*)  d_in[2];
    const float* sigw   = (const float*)d_in[3];
    const float* W1 = (const float*)d_in[4];  const float* b1 = (const float*)d_in[5];
    const float* W2 = (const float*)d_in[6];  const float* b2 = (const float*)d_in[7];
    const float* Wv = (const float*)d_in[8];  const float* sv = (const float*)d_in[9];  const float* bv = (const float*)d_in[10];
    const float* Wg = (const float*)d_in[11]; const float* sg = (const float*)d_in[12]; const float* bg = (const float*)d_in[13];
    const float* Wb = (const float*)d_in[14]; const float* sb = (const float*)d_in[15]; const float* bb = (const float*)d_in[16];
    const float* Wf1 = (const float*)d_in[17]; const float* sf1 = (const float*)d_in[18]; const float* bf1 = (const float*)d_in[19];
    const float* Wf2 = (const float*)d_in[20]; const float* sf2 = (const float*)d_in[21]; const float* bf2 = (const float*)d_in[22];
    const float* Wf3 = (const float*)d_in[23]; const float* bf3 = (const float*)d_in[24];
    const float* Ws  = (const float*)d_in[25]; const float* bs  = (const float*)d_in[26];
    const float* awp = (const float*)d_in[27];

    float* bufA; cudaGetSymbolAddress((void**)&bufA, g_bufA);
    float* bufB; cudaGetSymbolAddress((void**)&bufB, g_bufB);
    float* outp = (float*)d_out;

    // small path
    k_lang <<<16, 256>>>(flang, wmask, W1, b1, W2, b2);
    k_ssum <<<B_*C_, 128>>>(img);
    k_sigma<<<B_*NC_, 128>>>(Ws, bs, sigw);
    k_gbmax<<<B_*16, 256>>>(Wg, sg, bg, Wb, sb, bb, sigw);

    dim3 gg(HW_/128, C_/128, B_);
    // map_visu + g*t+bmax fused
    k_gemm<0><<<gg, 256>>>(Wv, img, bufA, sv, bv, nullptr, nullptr);
    k_l2norm<<<B_*HW_/128, 128>>>(bufA, bufB);
    // Wf1 cbs
    k_gemm<1><<<gg, 256>>>(Wf1, bufB, bufA, sf1, bf1, nullptr, nullptr);
    // Wf2 3x3 cbs
    k_conv3 <<<gg, 256>>>(Wf2, bufA, bufB, sf2, bf2);
    // Wf3 + residual
    k_gemm<2><<<gg, 256>>>(Wf3, bufB, bufA, nullptr, bf3, img, awp);
    // final l2norm -> out
    k_l2norm<<<B_*HW_/128, 128>>>(bufA, outp);
}